// round 5
// baseline (speedup 1.0000x reference)
#include <cuda_runtime.h>
#include <cstdint>

#define HID  1024
#define ITR  4096
#define MTOT 16384

// Intermediate activation buffer (ReLU(X@W1^T + b1)), 16384 x 4096 fp32 = 256 MiB.
__device__ float g_inter[(size_t)MTOT * (size_t)ITR];

#define BM 128
#define BN 128
#define BK 32
#define BKP 36                        // +4 pad: conflict-free fragment LDS
#define STAGES 3
#define TILE_F (BM * BKP)             // floats per (stage, operand) tile
#define SMEM_BYTES (STAGES * 2 * TILE_F * 4)   // 110592 B -> 2 CTAs/SM

__device__ __forceinline__ void cp_async16(uint32_t saddr, const void* gptr) {
    asm volatile("cp.async.cg.shared.global [%0], [%1], 16;\n" :: "r"(saddr), "l"(gptr));
}
__device__ __forceinline__ void cp_commit() {
    asm volatile("cp.async.commit_group;\n");
}
template <int N>
__device__ __forceinline__ void cp_wait() {
    asm volatile("cp.async.wait_group %0;\n" :: "n"(N));
}

// Split two consecutive f32 (one float2) into a packed bf16x2 "hi" register
// (bitwise truncation: exact in f32) and a packed bf16x2 "lo" residual register.
// a = hi + lo up to 2^-17 relative; dropping lo*lo in the MMA sum leaves ~2^-16.
__device__ __forceinline__ void split_bf16(const float* p, uint32_t& hi, uint32_t& lo) {
    float2 v = *(const float2*)p;
    uint32_t u0 = __float_as_uint(v.x), u1 = __float_as_uint(v.y);
    asm("prmt.b32 %0, %1, %2, 0x7632;" : "=r"(hi) : "r"(u0), "r"(u1));
    float r0 = __uint_as_float(u0 & 0xFFFF0000u);
    float r1 = __uint_as_float(u1 & 0xFFFF0000u);
    asm("cvt.rn.bf16x2.f32 %0, %1, %2;" : "=r"(lo) : "f"(v.y - r1), "f"(v.x - r0));
}

__device__ __forceinline__ void mma_bf16(float* d, const uint32_t* a, const uint32_t* b) {
    asm volatile(
        "mma.sync.aligned.m16n8k16.row.col.f32.bf16.bf16.f32 "
        "{%0,%1,%2,%3}, {%4,%5,%6,%7}, {%8,%9}, {%0,%1,%2,%3};\n"
        : "+f"(d[0]), "+f"(d[1]), "+f"(d[2]), "+f"(d[3])
        : "r"(a[0]), "r"(a[1]), "r"(a[2]), "r"(a[3]), "r"(b[0]), "r"(b[1]));
}

// C[M,N] = A[M,K] @ B[N,K]^T + bias[N], optional ReLU.
// 128 threads / CTA, warp grid 2x2, warp tile 64x64.
// Each logical f32 MMA realized as 3 bf16 m16n8k16 MMAs (hi*hi + lo*hi + hi*lo).
template <bool RELU>
__global__ void __launch_bounds__(128, 2) gemm_bias_bf16x3(
    const float* __restrict__ A, const float* __restrict__ Bm,
    const float* __restrict__ bias, float* __restrict__ C,
    int K, int N)
{
    extern __shared__ float sm[];
    const int tid  = threadIdx.x;
    const int lane = tid & 31;
    const int wid  = tid >> 5;
    const int wm   = wid >> 1;     // 0..1 : warp row (64 M each)
    const int wn   = wid & 1;      // 0..1 : warp col (64 N each)
    const int g    = lane >> 2;    // 0..7
    const int tg   = lane & 3;     // 0..3

    const int bm = blockIdx.y * BM;
    const int bn = blockIdx.x * BN;

    float acc[4][8][4];
#pragma unroll
    for (int i = 0; i < 4; i++)
#pragma unroll
        for (int j = 0; j < 8; j++)
#pragma unroll
            for (int c = 0; c < 4; c++) acc[i][j][c] = 0.f;

    const int KT = K / BK;
    const uint32_t s0 = (uint32_t)__cvta_generic_to_shared(sm);

    auto load_tile = [&](int kt, int stage) {
        const float* Ag = A  + (size_t)bm * K + (size_t)kt * BK;
        const float* Bg = Bm + (size_t)bn * K + (size_t)kt * BK;
        const uint32_t sA = s0 + (uint32_t)(stage * 2 * TILE_F) * 4;
        const uint32_t sB = sA + (uint32_t)TILE_F * 4;
#pragma unroll
        for (int t = 0; t < 8; t++) {
            int chunk = tid + t * 128;      // 0..1023
            int row = chunk >> 3;           // BK/4 = 8 chunks per row
            int c4  = chunk & 7;
            cp_async16(sA + (uint32_t)(row * BKP + c4 * 4) * 4, Ag + (size_t)row * K + c4 * 4);
            cp_async16(sB + (uint32_t)(row * BKP + c4 * 4) * 4, Bg + (size_t)row * K + c4 * 4);
        }
        cp_commit();
    };

    load_tile(0, 0);
    load_tile(1, 1);

    for (int kt = 0; kt < KT; kt++) {
        cp_wait<1>();          // stage kt landed
        __syncthreads();

        if (kt + 2 < KT) load_tile(kt + 2, (kt + 2) % STAGES);
        else             cp_commit();   // uniform group accounting

        const float* Asb = sm + (kt % STAGES) * 2 * TILE_F;
        const float* Bsb = Asb + TILE_F;

#pragma unroll
        for (int ks = 0; ks < BK / 16; ks++) {
            const int k0 = ks * 16;
            // Convert A fragments for this K=16 slab: 4 i-tiles x 4 regs (hi+lo).
            uint32_t Ah[4][4], Al[4][4];
#pragma unroll
            for (int i = 0; i < 4; i++) {
                const int r = wm * 64 + i * 16 + g;
                split_bf16(Asb + (r    ) * BKP + k0 + 2 * tg,     Ah[i][0], Al[i][0]);
                split_bf16(Asb + (r + 8) * BKP + k0 + 2 * tg,     Ah[i][1], Al[i][1]);
                split_bf16(Asb + (r    ) * BKP + k0 + 2 * tg + 8, Ah[i][2], Al[i][2]);
                split_bf16(Asb + (r + 8) * BKP + k0 + 2 * tg + 8, Ah[i][3], Al[i][3]);
            }
            // Per j: convert B (2 regs hi+lo), fire 12 MMAs, release B regs.
#pragma unroll
            for (int j = 0; j < 8; j++) {
                const int c = wn * 64 + j * 8 + g;
                uint32_t bh[2], bl[2];
                split_bf16(Bsb + c * BKP + k0 + 2 * tg,     bh[0], bl[0]);
                split_bf16(Bsb + c * BKP + k0 + 2 * tg + 8, bh[1], bl[1]);
#pragma unroll
                for (int i = 0; i < 4; i++) {
                    mma_bf16(acc[i][j], Ah[i], bh);   // hi * hi
                    mma_bf16(acc[i][j], Al[i], bh);   // lo * hi
                    mma_bf16(acc[i][j], Ah[i], bl);   // hi * lo
                }
            }
        }
    }

    // Epilogue: +bias, optional ReLU, float2 stores (same D layout as m16n8k8).
#pragma unroll
    for (int i = 0; i < 4; i++) {
        const int r0 = bm + wm * 64 + i * 16 + g;
#pragma unroll
        for (int j = 0; j < 8; j++) {
            const int c = bn + wn * 64 + j * 8 + tg * 2;
            const float bv0 = bias[c];
            const float bv1 = bias[c + 1];
            float v0 = acc[i][j][0] + bv0;
            float v1 = acc[i][j][1] + bv1;
            float v2 = acc[i][j][2] + bv0;
            float v3 = acc[i][j][3] + bv1;
            if (RELU) {
                v0 = fmaxf(v0, 0.f); v1 = fmaxf(v1, 0.f);
                v2 = fmaxf(v2, 0.f); v3 = fmaxf(v3, 0.f);
            }
            *(float2*)(C + (size_t)r0 * N + c)       = make_float2(v0, v1);
            *(float2*)(C + (size_t)(r0 + 8) * N + c) = make_float2(v2, v3);
        }
    }
}

extern "C" void kernel_launch(void* const* d_in, const int* in_sizes, int n_in,
                              void* d_out, int out_size) {
    (void)in_sizes; (void)n_in; (void)out_size;
    const float* x  = (const float*)d_in[0];  // [4,4096,1024] -> [16384,1024]
    const float* W1 = (const float*)d_in[1];  // [4096,1024]
    const float* b1 = (const float*)d_in[2];  // [4096]
    const float* W2 = (const float*)d_in[3];  // [1024,4096]
    const float* b2 = (const float*)d_in[4];  // [1024]
    float* out = (float*)d_out;               // [16384,1024]

    float* inter = nullptr;
    cudaGetSymbolAddress((void**)&inter, g_inter);

    cudaFuncSetAttribute(gemm_bias_bf16x3<true>,
                         cudaFuncAttributeMaxDynamicSharedMemorySize, SMEM_BYTES);
    cudaFuncSetAttribute(gemm_bias_bf16x3<false>,
                         cudaFuncAttributeMaxDynamicSharedMemorySize, SMEM_BYTES);

    // GEMM1: inter = ReLU(X @ W1^T + b1)   [16384, 4096], K=1024
    gemm_bias_bf16x3<true><<<dim3(ITR / BN, MTOT / BM), 128, SMEM_BYTES>>>(
        x, W1, b1, inter, HID, ITR);

    // GEMM2: out = inter @ W2^T + b2       [16384, 1024], K=4096
    gemm_bias_bf16x3<false><<<dim3(HID / BN, MTOT / BM), 128, SMEM_BYTES>>>(
        inter, W2, b2, out, ITR, HID);
}

// round 7
// speedup vs baseline: 4.4474x; 4.4474x over previous
#include <cuda_runtime.h>
#include <cstdint>

#define HID  1024
#define ITR  4096
#define MTOT 16384

// Scratch (allowed: __device__ globals). inter = ReLU(X@W1^T+b1), plus
// pre-rounded (tf32-rna via +0x1000 bump) copies of X, W1, W2.
__device__ float g_inter[(size_t)MTOT * (size_t)ITR];
__device__ float g_xb[(size_t)MTOT * (size_t)HID];
__device__ float g_w1b[(size_t)ITR * (size_t)HID];
__device__ float g_w2b[(size_t)HID * (size_t)ITR];

// tcgen05 only exists in arch-specific device passes (sm_103a / sm_100a).
#if defined(__CUDA_ARCH_FEAT_SM103_ALL) || defined(__CUDA_ARCH_FEAT_SM100_ALL)
#define HAS_TC05 1
#else
#define HAS_TC05 0
#endif

// ---------------- smem layout ----------------
#define NSTAGE 4
#define BK 32                      // K per stage (4 x tf32 K=8 MMAs)
#define TILE_B 16384               // 128 rows x 128 bytes per operand stage
#define SM_TMEM  0
#define SM_FULL  16                // full[s] on leader (count 2)
#define SM_FLOC  48                // local cp.async barrier (count 256)
#define SM_EMPTY 80                // stage free (count 1, commit multicast)
#define SM_DONE  112               // all MMAs done
#define SM_A 1024
#define SM_B (SM_A + NSTAGE * TILE_B)
#define SMEM_TOTAL (SM_B + NSTAGE * TILE_B)   // 132096 B

// idesc: c=F32(1)<<4 | a=TF32(2)<<7 | b=TF32(2)<<10 | (N/8=32)<<17 | (M/16=16)<<24
#define IDESC_TF32 0x10400910u
static constexpr uint64_t DESC_BASE =       // SW128 K-major: layout=2, ver=1, SBO=64, LBO=1
    (2ull << 61) | (1ull << 46) | (64ull << 32) | (1ull << 16);

// ---------------- common helpers ----------------
__device__ __forceinline__ uint32_t smem_u32(const void* p) {
    return (uint32_t)__cvta_generic_to_shared(p);
}
__device__ __forceinline__ void cp16(uint32_t d, const void* s) {
    asm volatile("cp.async.cg.shared.global [%0], [%1], 16;" :: "r"(d), "l"(s));
}
__device__ __forceinline__ void cp_commit() {
    asm volatile("cp.async.commit_group;");
}
template <int N>
__device__ __forceinline__ void cp_wait() {
    asm volatile("cp.async.wait_group %0;" :: "n"(N));
}
__device__ __forceinline__ void st_cs4(float* p, float a, float b, float c, float d) {
    asm volatile("st.global.cs.v4.f32 [%0], {%1,%2,%3,%4};"
                 :: "l"(p), "f"(a), "f"(b), "f"(c), "f"(d) : "memory");
}
// tf32 round-to-nearest via half-ulp bump; HW truncates low 13 mantissa bits,
// so trunc(bits + 0x1000) == rna(tf32). Proven bit-identical to cvt.rna in R1/R3.
__device__ __forceinline__ float bumpf(float f) {
    return __uint_as_float(__float_as_uint(f) + 0x1000u);
}

// ---------------- prepass: elementwise tf32-rna pre-round ----------------
__global__ void __launch_bounds__(256) bump_tf32_kernel(const float4* __restrict__ in,
                                                        float4* __restrict__ out, int n4) {
    int i = blockIdx.x * blockDim.x + threadIdx.x;
    if (i < n4) {
        float4 v = in[i];
        v.x = bumpf(v.x); v.y = bumpf(v.y); v.z = bumpf(v.z); v.w = bumpf(v.w);
        out[i] = v;
    }
}

#if HAS_TC05
// ---------------- tcgen05 helpers (arch-specific pass only) ----------------
__device__ __forceinline__ uint32_t ctarank() {
    uint32_t r; asm("mov.u32 %0, %%cluster_ctarank;" : "=r"(r)); return r;
}
__device__ __forceinline__ bool elect_one() {
    uint32_t p;
    asm volatile("{\n\t.reg .pred P;\n\telect.sync _|P, 0xFFFFFFFF;\n\tselp.b32 %0, 1, 0, P;\n\t}"
                 : "=r"(p));
    return p != 0;
}
__device__ __forceinline__ void mbar_init(uint32_t a, uint32_t cnt) {
    asm volatile("mbarrier.init.shared.b64 [%0], %1;" :: "r"(a), "r"(cnt) : "memory");
}
__device__ __forceinline__ void mbar_arrive_cluster(uint32_t local_addr, uint32_t rank) {
    asm volatile("{\n\t.reg .b32 ra;\n\tmapa.shared::cluster.u32 ra, %0, %1;\n\t"
                 "mbarrier.arrive.shared::cluster.b64 _, [ra];\n\t}"
                 :: "r"(local_addr), "r"(rank) : "memory");
}
__device__ __forceinline__ void wait_parity(uint32_t a, uint32_t ph) {
    asm volatile("{\n\t.reg .pred P;\n"
                 "W_%=:\n\tmbarrier.try_wait.parity.acquire.cta.shared::cta.b64 P, [%0], %1, 0x989680;\n"
                 "\t@P bra D_%=;\n\tbra W_%=;\nD_%=:\n\t}"
                 :: "r"(a), "r"(ph) : "memory");
}
__device__ __forceinline__ void cp_arrive_noinc(uint32_t bar) {
    asm volatile("cp.async.mbarrier.arrive.noinc.shared::cta.b64 [%0];" :: "r"(bar) : "memory");
}
__device__ __forceinline__ void mma_cg2_tf32(uint32_t d, uint64_t ad, uint64_t bd,
                                             uint32_t idesc, uint32_t en) {
    asm volatile("{\n\t.reg .pred p;\n\tsetp.ne.u32 p, %4, 0;\n\t"
                 "tcgen05.mma.cta_group::2.kind::tf32 [%0], %1, %2, %3, "
                 "{%5,%5,%5,%5,%5,%5,%5,%5}, p;\n\t}"
                 :: "r"(d), "l"(ad), "l"(bd), "r"(idesc), "r"(en), "r"(0u) : "memory");
}
__device__ __forceinline__ void commit_mc(uint32_t bar) {
    asm volatile("tcgen05.commit.cta_group::2.mbarrier::arrive::one.shared::cluster.multicast::cluster.b64 [%0], %1;"
                 :: "r"(bar), "h"((uint16_t)3) : "memory");
}
__device__ __forceinline__ void tmem_alloc_cg2(uint32_t addr, uint32_t ncols) {
    asm volatile("tcgen05.alloc.cta_group::2.sync.aligned.shared::cta.b32 [%0], %1;"
                 :: "r"(addr), "r"(ncols) : "memory");
}
__device__ __forceinline__ void tmem_dealloc_cg2(uint32_t tmem, uint32_t ncols) {
    asm volatile("tcgen05.dealloc.cta_group::2.sync.aligned.b32 %0, %1;" :: "r"(tmem), "r"(ncols));
}
__device__ __forceinline__ void tmem_relinquish_cg2() {
    asm volatile("tcgen05.relinquish_alloc_permit.cta_group::2.sync.aligned;");
}
__device__ __forceinline__ void fence_after_sync() {
    asm volatile("tcgen05.fence::after_thread_sync;" ::: "memory");
}
__device__ __forceinline__ void fence_proxy_async_cta() {
    asm volatile("fence.proxy.async.shared::cta;" ::: "memory");
}
__device__ __forceinline__ void cluster_sync() {
    asm volatile("barrier.cluster.arrive.aligned;" ::: "memory");
    asm volatile("barrier.cluster.wait.aligned;" ::: "memory");
}
__device__ __forceinline__ void wait_ld() {
    asm volatile("tcgen05.wait::ld.sync.aligned;" ::: "memory");
}
#define LDTM_X32(r, taddr) \
    asm volatile( \
        "tcgen05.ld.sync.aligned.32x32b.x32.b32 " \
        "{%0, %1, %2, %3, %4, %5, %6, %7, " \
        " %8, %9, %10, %11, %12, %13, %14, %15, " \
        " %16, %17, %18, %19, %20, %21, %22, %23, " \
        " %24, %25, %26, %27, %28, %29, %30, %31}, [%32];" \
        : "=r"((r)[0]),  "=r"((r)[1]),  "=r"((r)[2]),  "=r"((r)[3]), \
          "=r"((r)[4]),  "=r"((r)[5]),  "=r"((r)[6]),  "=r"((r)[7]), \
          "=r"((r)[8]),  "=r"((r)[9]),  "=r"((r)[10]), "=r"((r)[11]), \
          "=r"((r)[12]), "=r"((r)[13]), "=r"((r)[14]), "=r"((r)[15]), \
          "=r"((r)[16]), "=r"((r)[17]), "=r"((r)[18]), "=r"((r)[19]), \
          "=r"((r)[20]), "=r"((r)[21]), "=r"((r)[22]), "=r"((r)[23]), \
          "=r"((r)[24]), "=r"((r)[25]), "=r"((r)[26]), "=r"((r)[27]), \
          "=r"((r)[28]), "=r"((r)[29]), "=r"((r)[30]), "=r"((r)[31]) \
        : "r"(taddr))
#else
// ---------------- fallback helpers (generic pass): legacy mma.sync tf32 ----------
// Operands are pre-rounded in gmem, so no bump here.
__device__ __forceinline__ void mma_tf32(float* d, const uint32_t* a, const uint32_t* b) {
    asm volatile(
        "mma.sync.aligned.m16n8k8.row.col.f32.tf32.tf32.f32 "
        "{%0,%1,%2,%3}, {%4,%5,%6,%7}, {%8,%9}, {%0,%1,%2,%3};\n"
        : "+f"(d[0]), "+f"(d[1]), "+f"(d[2]), "+f"(d[3])
        : "r"(a[0]), "r"(a[1]), "r"(a[2]), "r"(a[3]), "r"(b[0]), "r"(b[1]));
}
#endif

// ---------------- kernel ----------------
// grid = (2, N/256, M/256), cluster (2,1,1), 288 threads.
// tcgen05 path: CTA pair computes C[256,256]; warps 0-7 produce, warp 8 issues MMA.
// RELU template also bumps the stored value (pre-rounds inter for GEMM2).
template <bool RELU>
__global__ void __launch_bounds__(288, 1) __cluster_dims__(2, 1, 1)
ffn_gemm(const float* __restrict__ A, const float* __restrict__ Bm,
         const float* __restrict__ bias, float* __restrict__ C,
         int K, int N)
{
#if HAS_TC05
    extern __shared__ __align__(1024) char smem[];
    const uint32_t sb  = smem_u32(smem);
    const int tid = threadIdx.x;
    const int wid = tid >> 5;
    const uint32_t rank = ctarank();

    const int m0 = blockIdx.z * 256 + (int)rank * 128;   // A rows this CTA loads
    const int n0 = blockIdx.y * 256 + (int)rank * 128;   // B rows this CTA loads
    const int KT = K / BK;

    if (wid == 8) {
        tmem_alloc_cg2(sb + SM_TMEM, 256);
        tmem_relinquish_cg2();
    }
    if (tid == 0) {
#pragma unroll
        for (int s = 0; s < NSTAGE; s++) {
            mbar_init(sb + SM_FULL  + s * 8, 2);
            mbar_init(sb + SM_FLOC  + s * 8, 256);
            mbar_init(sb + SM_EMPTY + s * 8, 1);
        }
        mbar_init(sb + SM_DONE, 1);
    }
    __syncthreads();
    uint32_t tmem;
    asm volatile("ld.shared.b32 %0, [%1];" : "=r"(tmem) : "r"(sb + SM_TMEM));
    cluster_sync();   // peer barriers live before any cluster arrive / commit

    if (tid < 256) {
        // -------- producer: 8 x cp.async(16B) per stage per thread --------
        uint32_t swoff[4];
        const float *pa[4], *pb[4];
#pragma unroll
        for (int i = 0; i < 4; i++) {
            int chunk = tid + i * 256;          // row=chunk/8, 16B col=chunk%8
            int row = chunk >> 3, c = chunk & 7;
            uint32_t off = (uint32_t)(row * 128 + c * 16);
            swoff[i] = off ^ ((off >> 3) & 0x70);
            pa[i] = A  + (size_t)(m0 + row) * K + c * 4;
            pb[i] = Bm + (size_t)(n0 + row) * K + c * 4;
        }
        int es = 0; uint32_t ep = 1;            // fresh barrier: parity-1 passes
        for (int kt = 0; kt < KT; kt++) {
            wait_parity(sb + SM_EMPTY + es * 8, ep);
            const uint32_t sa  = sb + SM_A + es * TILE_B;
            const uint32_t sbt = sb + SM_B + es * TILE_B;
#pragma unroll
            for (int i = 0; i < 4; i++) {
                cp16(sa  + swoff[i], pa[i]);
                cp16(sbt + swoff[i], pb[i]);
                pa[i] += BK; pb[i] += BK;
            }
            cp_arrive_noinc(sb + SM_FLOC + es * 8);
            if (++es == NSTAGE) { es = 0; ep ^= 1; }
        }
    } else if (wid == 8) {
        if (elect_one()) {
            int ls = 0; uint32_t lp = 0;        // local-full cursor
            int fs = 0; uint32_t fp = 0;        // pair-full cursor (rank 0)
            for (int kt = 0; kt < KT; kt++) {
                wait_parity(sb + SM_FLOC + ls * 8, lp);       // own tiles landed
                fence_proxy_async_cta();
                mbar_arrive_cluster(sb + SM_FULL + ls * 8, 0); // notify leader
                if (rank == 0) {
                    wait_parity(sb + SM_FULL + fs * 8, fp);    // both CTAs ready
                    fence_after_sync();
                    const uint64_t ad = DESC_BASE | (((sb + SM_A + fs * TILE_B) >> 4) & 0x3FFF);
                    const uint64_t bd = DESC_BASE | (((sb + SM_B + fs * TILE_B) >> 4) & 0x3FFF);
#pragma unroll
                    for (int ks = 0; ks < 4; ks++)             // 4 x K=8 tf32 MMAs
                        mma_cg2_tf32(tmem, ad + ks * 2, bd + ks * 2,
                                     IDESC_TF32, (kt > 0 || ks > 0) ? 1u : 0u);
                    commit_mc((kt == KT - 1) ? (sb + SM_DONE)
                                             : (sb + SM_EMPTY + fs * 8));
                    if (++fs == NSTAGE) { fs = 0; fp ^= 1; }
                }
                if (++ls == NSTAGE) { ls = 0; lp ^= 1; }
            }
        }
    }

    // -------- epilogue: 8 warps, two warpgroups split the 256 columns --------
    if (tid < 256) {
        wait_parity(sb + SM_DONE, 0);
        fence_after_sync();
        const int sub  = wid & 3;               // TMEM subpartition == SMSP
        const int colh = (wid >> 2) * 128;      // column half
        const int grow = m0 + sub * 32 + (tid & 31);
        float* crow = C + (size_t)grow * N;
#pragma unroll
        for (int c4 = 0; c4 < 4; c4++) {
            uint32_t r[32];
            LDTM_X32(r, tmem + colh + c4 * 32);
            wait_ld();
            const int gc0 = blockIdx.y * 256 + colh + c4 * 32;
#pragma unroll
            for (int j = 0; j < 32; j += 4) {
                float4 bv = *(const float4*)(bias + gc0 + j);
                float v0 = __uint_as_float(r[j])     + bv.x;
                float v1 = __uint_as_float(r[j + 1]) + bv.y;
                float v2 = __uint_as_float(r[j + 2]) + bv.z;
                float v3 = __uint_as_float(r[j + 3]) + bv.w;
                if (RELU) {
                    // ReLU + pre-round (tf32-rna bump) so GEMM2's HW truncation
                    // of inter becomes round-to-nearest.
                    v0 = bumpf(fmaxf(v0, 0.f)); v1 = bumpf(fmaxf(v1, 0.f));
                    v2 = bumpf(fmaxf(v2, 0.f)); v3 = bumpf(fmaxf(v3, 0.f));
                }
                st_cs4(crow + gc0 + j, v0, v1, v2, v3);
            }
        }
    }
    __syncthreads();
    if (wid == 8) tmem_dealloc_cg2(tmem, 256);
    cluster_sync();
#else
    // ================= fallback: legacy mma.sync tf32 (generic PTX pass) ========
    extern __shared__ float sm[];
    const int tid  = threadIdx.x;
    const int lane = tid & 31;
    const int wid  = tid >> 5;
    const int m0 = blockIdx.z * 256 + blockIdx.x * 128;
    const int nb = blockIdx.y * 256;
    const int KT = K / BK;
    const int AT = 128 * 36;                 // A stage floats
    const int BT = 256 * 36;                 // B stage floats
    const uint32_t s0 = smem_u32(sm);

    float acc[4][8][4];
    if (tid < 256) {
#pragma unroll
        for (int i = 0; i < 4; i++)
#pragma unroll
            for (int j = 0; j < 8; j++)
#pragma unroll
                for (int c = 0; c < 4; c++) acc[i][j][c] = 0.f;
    }

    auto load_tile = [&](int kt, int st) {
        if (tid < 256) {
            const float* Ag = A  + (size_t)m0 * K + (size_t)kt * BK;
            const float* Bg = Bm + (size_t)nb * K + (size_t)kt * BK;
            const uint32_t sA = s0 + (uint32_t)(st * (AT + BT)) * 4;
            const uint32_t sB = sA + (uint32_t)AT * 4;
#pragma unroll
            for (int t = 0; t < 4; t++) {        // A: 1024 chunks
                int ch = tid + t * 256; int row = ch >> 3, c4 = ch & 7;
                cp16(sA + (uint32_t)(row * 36 + c4 * 4) * 4, Ag + (size_t)row * K + c4 * 4);
            }
#pragma unroll
            for (int t = 0; t < 8; t++) {        // B: 2048 chunks
                int ch = tid + t * 256; int row = ch >> 3, c4 = ch & 7;
                cp16(sB + (uint32_t)(row * 36 + c4 * 4) * 4, Bg + (size_t)row * K + c4 * 4);
            }
        }
        cp_commit();
    };

    load_tile(0, 0);
    for (int kt = 0; kt < KT; kt++) {
        const int st = kt & 1;
        if (kt + 1 < KT) { load_tile(kt + 1, st ^ 1); cp_wait<1>(); }
        else             { cp_wait<0>(); }
        __syncthreads();
        if (tid < 256) {
            const float* As = sm + st * (AT + BT);
            const float* Bs = As + AT;
            const int wm = wid >> 2, wn = wid & 3;
            const int g = lane >> 2, tg = lane & 3;
#pragma unroll
            for (int ks = 0; ks < 4; ks++) {
                const int k0 = ks * 8;
                uint32_t af[4][4], bf[8][2];
#pragma unroll
                for (int i = 0; i < 4; i++) {
                    const int r = wm * 64 + i * 16 + g;
                    af[i][0] = __float_as_uint(As[(r    ) * 36 + k0 + tg    ]);
                    af[i][1] = __float_as_uint(As[(r + 8) * 36 + k0 + tg    ]);
                    af[i][2] = __float_as_uint(As[(r    ) * 36 + k0 + tg + 4]);
                    af[i][3] = __float_as_uint(As[(r + 8) * 36 + k0 + tg + 4]);
                }
#pragma unroll
                for (int j = 0; j < 8; j++) {
                    const int c = wn * 64 + j * 8 + g;
                    bf[j][0] = __float_as_uint(Bs[c * 36 + k0 + tg    ]);
                    bf[j][1] = __float_as_uint(Bs[c * 36 + k0 + tg + 4]);
                }
#pragma unroll
                for (int i = 0; i < 4; i++)
#pragma unroll
                    for (int j = 0; j < 8; j++)
                        mma_tf32(acc[i][j], af[i], bf[j]);
            }
        }
        __syncthreads();
    }
    if (tid < 256) {
        const int wm = wid >> 2, wn = wid & 3;
        const int g = lane >> 2, tg = lane & 3;
#pragma unroll
        for (int i = 0; i < 4; i++) {
            const int r0 = m0 + wm * 64 + i * 16 + g;
#pragma unroll
            for (int j = 0; j < 8; j++) {
                const int c = nb + wn * 64 + j * 8 + tg * 2;
                const float bv0 = bias[c], bv1 = bias[c + 1];
                float v0 = acc[i][j][0] + bv0, v1 = acc[i][j][1] + bv1;
                float v2 = acc[i][j][2] + bv0, v3 = acc[i][j][3] + bv1;
                if (RELU) {
                    v0 = bumpf(fmaxf(v0, 0.f)); v1 = bumpf(fmaxf(v1, 0.f));
                    v2 = bumpf(fmaxf(v2, 0.f)); v3 = bumpf(fmaxf(v3, 0.f));
                }
                *(float2*)(C + (size_t)r0 * N + c)       = make_float2(v0, v1);
                *(float2*)(C + (size_t)(r0 + 8) * N + c) = make_float2(v2, v3);
            }
        }
    }
#endif
}

// ---------------- launch ----------------
extern "C" void kernel_launch(void* const* d_in, const int* in_sizes, int n_in,
                              void* d_out, int out_size) {
    (void)in_sizes; (void)n_in; (void)out_size;
    const float* x  = (const float*)d_in[0];  // [4,4096,1024] -> [16384,1024]
    const float* W1 = (const float*)d_in[1];  // [4096,1024]
    const float* b1 = (const float*)d_in[2];  // [4096]
    const float* W2 = (const float*)d_in[3];  // [1024,4096]
    const float* b2 = (const float*)d_in[4];  // [1024]
    float* out = (float*)d_out;               // [16384,1024]

    float *inter, *xb, *w1b, *w2b;
    cudaGetSymbolAddress((void**)&inter, g_inter);
    cudaGetSymbolAddress((void**)&xb,  g_xb);
    cudaGetSymbolAddress((void**)&w1b, g_w1b);
    cudaGetSymbolAddress((void**)&w2b, g_w2b);

    cudaFuncSetAttribute(ffn_gemm<true>,
                         cudaFuncAttributeMaxDynamicSharedMemorySize, SMEM_TOTAL);
    cudaFuncSetAttribute(ffn_gemm<false>,
                         cudaFuncAttributeMaxDynamicSharedMemorySize, SMEM_TOTAL);

    // Prepass: tf32-rna pre-round of all MMA operands (inter handled in epilogue).
    {
        int n4;
        n4 = MTOT * HID / 4;
        bump_tf32_kernel<<<(n4 + 255) / 256, 256>>>((const float4*)x,  (float4*)xb,  n4);
        n4 = ITR * HID / 4;
        bump_tf32_kernel<<<(n4 + 255) / 256, 256>>>((const float4*)W1, (float4*)w1b, n4);
        n4 = HID * ITR / 4;
        bump_tf32_kernel<<<(n4 + 255) / 256, 256>>>((const float4*)W2, (float4*)w2b, n4);
    }

    // GEMM1: inter = bump(ReLU(X @ W1^T + b1))  [16384,4096], K=1024
    ffn_gemm<true><<<dim3(2, ITR / 256, MTOT / 256), 288, SMEM_TOTAL>>>(
        xb, w1b, b1, inter, HID, ITR);

    // GEMM2: out = inter @ W2^T + b2            [16384,1024], K=4096
    ffn_gemm<false><<<dim3(2, HID / 256, MTOT / 256), 288, SMEM_TOTAL>>>(
        inter, w2b, b2, out, ITR, HID);
}

// round 8
// speedup vs baseline: 4.7271x; 1.0629x over previous
#include <cuda_runtime.h>
#include <cstdint>

#define HID  1024
#define ITR  4096
#define MTOT 16384

// Scratch: inter = ReLU(X@W1^T+b1) (pre-bumped), plus tf32-rna pre-rounded X/W1/W2.
__device__ float g_inter[(size_t)MTOT * (size_t)ITR];
__device__ float g_xb[(size_t)MTOT * (size_t)HID];
__device__ float g_w1b[(size_t)ITR * (size_t)HID];
__device__ float g_w2b[(size_t)HID * (size_t)ITR];

#if defined(__CUDA_ARCH_FEAT_SM103_ALL) || defined(__CUDA_ARCH_FEAT_SM100_ALL)
#define HAS_TC05 1
#else
#define HAS_TC05 0
#endif

// ---------------- smem layout ----------------
#define NSTAGE 6
#define BK 32                      // K per stage (4 x tf32 K=8 MMAs)
#define TILE_B 16384               // 128 rows x 128 B per operand stage
#define SM_TMEM  0
#define SM_FULL  16                // [6] pair-full on leader (count 2)
#define SM_FLOC  64                // [6] local cp.async barrier (count 128)
#define SM_EMPTY 112               // [6] stage free (commit multicast)
#define SM_DONE  160               // [2] tile done per D buffer (commit multicast)
#define SM_EPIF  176               // [2] epilogue freed D buffer (count 256, on leader)
#define SM_A 1024
#define SM_B (SM_A + NSTAGE * TILE_B)
#define SMEM_TOTAL (SM_B + NSTAGE * TILE_B)   // 197632 B

// idesc: c=F32(1)<<4 | a=TF32(2)<<7 | b=TF32(2)<<10 | (N/8=32)<<17 | (M/16=16)<<24
#define IDESC_TF32 0x10400910u
static constexpr uint64_t DESC_BASE =       // SW128 K-major: layout=2, ver=1, SBO=64, LBO=1
    (2ull << 61) | (1ull << 46) | (64ull << 32) | (1ull << 16);

// ---------------- common helpers ----------------
__device__ __forceinline__ uint32_t smem_u32(const void* p) {
    return (uint32_t)__cvta_generic_to_shared(p);
}
__device__ __forceinline__ void cp16(uint32_t d, const void* s) {
    asm volatile("cp.async.cg.shared.global [%0], [%1], 16;" :: "r"(d), "l"(s));
}
__device__ __forceinline__ void st_cs4(float* p, float a, float b, float c, float d) {
    asm volatile("st.global.cs.v4.f32 [%0], {%1,%2,%3,%4};"
                 :: "l"(p), "f"(a), "f"(b), "f"(c), "f"(d) : "memory");
}
// tf32 rna via half-ulp bump (HW truncates low 13 mantissa bits).
__device__ __forceinline__ float bumpf(float f) {
    return __uint_as_float(__float_as_uint(f) + 0x1000u);
}

// ---------------- prepass ----------------
__global__ void __launch_bounds__(256) bump_tf32_kernel(const float4* __restrict__ in,
                                                        float4* __restrict__ out, int n4) {
    int i = blockIdx.x * blockDim.x + threadIdx.x;
    if (i < n4) {
        float4 v = in[i];
        v.x = bumpf(v.x); v.y = bumpf(v.y); v.z = bumpf(v.z); v.w = bumpf(v.w);
        out[i] = v;
    }
}

#if HAS_TC05
// ---------------- tcgen05 helpers ----------------
__device__ __forceinline__ uint32_t ctarank() {
    uint32_t r; asm("mov.u32 %0, %%cluster_ctarank;" : "=r"(r)); return r;
}
__device__ __forceinline__ bool elect_one() {
    uint32_t p;
    asm volatile("{\n\t.reg .pred P;\n\telect.sync _|P, 0xFFFFFFFF;\n\tselp.b32 %0, 1, 0, P;\n\t}"
                 : "=r"(p));
    return p != 0;
}
__device__ __forceinline__ void mbar_init(uint32_t a, uint32_t cnt) {
    asm volatile("mbarrier.init.shared.b64 [%0], %1;" :: "r"(a), "r"(cnt) : "memory");
}
__device__ __forceinline__ void mbar_arrive_cluster(uint32_t local_addr, uint32_t rank) {
    asm volatile("{\n\t.reg .b32 ra;\n\tmapa.shared::cluster.u32 ra, %0, %1;\n\t"
                 "mbarrier.arrive.shared::cluster.b64 _, [ra];\n\t}"
                 :: "r"(local_addr), "r"(rank) : "memory");
}
__device__ __forceinline__ void wait_parity(uint32_t a, uint32_t ph) {
    asm volatile("{\n\t.reg .pred P;\n"
                 "W_%=:\n\tmbarrier.try_wait.parity.acquire.cta.shared::cta.b64 P, [%0], %1, 0x989680;\n"
                 "\t@P bra D_%=;\n\tbra W_%=;\nD_%=:\n\t}"
                 :: "r"(a), "r"(ph) : "memory");
}
__device__ __forceinline__ void cp_arrive_noinc(uint32_t bar) {
    asm volatile("cp.async.mbarrier.arrive.noinc.shared::cta.b64 [%0];" :: "r"(bar) : "memory");
}
__device__ __forceinline__ void mma_cg2_tf32(uint32_t d, uint64_t ad, uint64_t bd,
                                             uint32_t idesc, uint32_t en) {
    asm volatile("{\n\t.reg .pred p;\n\tsetp.ne.u32 p, %4, 0;\n\t"
                 "tcgen05.mma.cta_group::2.kind::tf32 [%0], %1, %2, %3, "
                 "{%5,%5,%5,%5,%5,%5,%5,%5}, p;\n\t}"
                 :: "r"(d), "l"(ad), "l"(bd), "r"(idesc), "r"(en), "r"(0u) : "memory");
}
__device__ __forceinline__ void commit_mc(uint32_t bar) {
    asm volatile("tcgen05.commit.cta_group::2.mbarrier::arrive::one.shared::cluster.multicast::cluster.b64 [%0], %1;"
                 :: "r"(bar), "h"((uint16_t)3) : "memory");
}
__device__ __forceinline__ void tmem_alloc_cg2(uint32_t addr, uint32_t ncols) {
    asm volatile("tcgen05.alloc.cta_group::2.sync.aligned.shared::cta.b32 [%0], %1;"
                 :: "r"(addr), "r"(ncols) : "memory");
}
__device__ __forceinline__ void tmem_dealloc_cg2(uint32_t tmem, uint32_t ncols) {
    asm volatile("tcgen05.dealloc.cta_group::2.sync.aligned.b32 %0, %1;" :: "r"(tmem), "r"(ncols));
}
__device__ __forceinline__ void tmem_relinquish_cg2() {
    asm volatile("tcgen05.relinquish_alloc_permit.cta_group::2.sync.aligned;");
}
__device__ __forceinline__ void fence_after_sync() {
    asm volatile("tcgen05.fence::after_thread_sync;" ::: "memory");
}
__device__ __forceinline__ void fence_before_sync() {
    asm volatile("tcgen05.fence::before_thread_sync;" ::: "memory");
}
__device__ __forceinline__ void fence_proxy_async_cta() {
    asm volatile("fence.proxy.async.shared::cta;" ::: "memory");
}
__device__ __forceinline__ void cluster_sync() {
    asm volatile("barrier.cluster.arrive.aligned;" ::: "memory");
    asm volatile("barrier.cluster.wait.aligned;" ::: "memory");
}
__device__ __forceinline__ void wait_ld() {
    asm volatile("tcgen05.wait::ld.sync.aligned;" ::: "memory");
}
#define LDTM_X32(r, taddr) \
    asm volatile( \
        "tcgen05.ld.sync.aligned.32x32b.x32.b32 " \
        "{%0, %1, %2, %3, %4, %5, %6, %7, " \
        " %8, %9, %10, %11, %12, %13, %14, %15, " \
        " %16, %17, %18, %19, %20, %21, %22, %23, " \
        " %24, %25, %26, %27, %28, %29, %30, %31}, [%32];" \
        : "=r"((r)[0]),  "=r"((r)[1]),  "=r"((r)[2]),  "=r"((r)[3]), \
          "=r"((r)[4]),  "=r"((r)[5]),  "=r"((r)[6]),  "=r"((r)[7]), \
          "=r"((r)[8]),  "=r"((r)[9]),  "=r"((r)[10]), "=r"((r)[11]), \
          "=r"((r)[12]), "=r"((r)[13]), "=r"((r)[14]), "=r"((r)[15]), \
          "=r"((r)[16]), "=r"((r)[17]), "=r"((r)[18]), "=r"((r)[19]), \
          "=r"((r)[20]), "=r"((r)[21]), "=r"((r)[22]), "=r"((r)[23]), \
          "=r"((r)[24]), "=r"((r)[25]), "=r"((r)[26]), "=r"((r)[27]), \
          "=r"((r)[28]), "=r"((r)[29]), "=r"((r)[30]), "=r"((r)[31]) \
        : "r"(taddr))
#else
__device__ __forceinline__ void mma_tf32(float* d, const uint32_t* a, const uint32_t* b) {
    asm volatile(
        "mma.sync.aligned.m16n8k8.row.col.f32.tf32.tf32.f32 "
        "{%0,%1,%2,%3}, {%4,%5,%6,%7}, {%8,%9}, {%0,%1,%2,%3};\n"
        : "+f"(d[0]), "+f"(d[1]), "+f"(d[2]), "+f"(d[3])
        : "r"(a[0]), "r"(a[1]), "r"(a[2]), "r"(a[3]), "r"(b[0]), "r"(b[1]));
}
#endif

// ---------------- kernel ----------------
// grid = (2, M/256, 1), cluster (2,1,1), 288 threads. Persistent pair: owns one
// 256-row M-panel, sweeps TPP N-tiles of 256. Warps 0-3 produce, 4-7 epilogue,
// 8 issues MMA into double-buffered TMEM D (cols 0-255 / 256-511).
template <bool RELU>
__global__ void __launch_bounds__(288, 1) __cluster_dims__(2, 1, 1)
ffn_gemm(const float* __restrict__ A, const float* __restrict__ Bm,
         const float* __restrict__ bias, float* __restrict__ C,
         int K, int N, int TPP)
{
#if HAS_TC05
    extern __shared__ __align__(1024) char smem[];
    const uint32_t sb  = smem_u32(smem);
    const int tid = threadIdx.x;
    const int wid = tid >> 5;
    const uint32_t rank = ctarank();

    const int m0 = blockIdx.y * 256 + (int)rank * 128;   // this CTA's A rows
    const int KT = K / BK;

    if (wid == 8) {
        tmem_alloc_cg2(sb + SM_TMEM, 512);
        tmem_relinquish_cg2();
    }
    if (tid == 0) {
#pragma unroll
        for (int s = 0; s < NSTAGE; s++) {
            mbar_init(sb + SM_FULL  + s * 8, 2);
            mbar_init(sb + SM_FLOC  + s * 8, 128);
            mbar_init(sb + SM_EMPTY + s * 8, 1);
        }
        mbar_init(sb + SM_DONE,      1);
        mbar_init(sb + SM_DONE + 8,  1);
        mbar_init(sb + SM_EPIF,      256);
        mbar_init(sb + SM_EPIF + 8,  256);
    }
    __syncthreads();
    uint32_t tmem;
    asm volatile("ld.shared.b32 %0, [%1];" : "=r"(tmem) : "r"(sb + SM_TMEM));
    cluster_sync();   // peer barriers live before any cluster arrive / commit

    if (wid < 4) {
        // ======== producers: 128 threads, 16 cp16 per stage each ========
        uint32_t swoff[8]; int rowc[8], colc[8];
        const float* paB[8];
#pragma unroll
        for (int i = 0; i < 8; i++) {
            int chunk = tid + i * 128;          // 0..1023: row=chunk/8, 16B col=chunk%8
            rowc[i] = chunk >> 3; colc[i] = chunk & 7;
            uint32_t off = (uint32_t)(rowc[i] * 128 + colc[i] * 16);
            swoff[i] = off ^ ((off >> 3) & 0x70);
            paB[i] = A + (size_t)(m0 + rowc[i]) * K + colc[i] * 4;
        }
        int es = 0; uint32_t ep = 1;            // fresh barrier: parity-1 passes
        for (int t = 0; t < TPP; t++) {
            const int n0 = t * 256 + (int)rank * 128;
            const float *pa[8], *pb[8];
#pragma unroll
            for (int i = 0; i < 8; i++) {
                pa[i] = paB[i];
                pb[i] = Bm + (size_t)(n0 + rowc[i]) * K + colc[i] * 4;
            }
            for (int kt = 0; kt < KT; kt++) {
                wait_parity(sb + SM_EMPTY + es * 8, ep);
                const uint32_t sa  = sb + SM_A + es * TILE_B;
                const uint32_t sbt = sb + SM_B + es * TILE_B;
#pragma unroll
                for (int i = 0; i < 8; i++) {
                    cp16(sa  + swoff[i], pa[i]);
                    cp16(sbt + swoff[i], pb[i]);
                    pa[i] += BK; pb[i] += BK;
                }
                cp_arrive_noinc(sb + SM_FLOC + es * 8);
                if (++es == NSTAGE) { es = 0; ep ^= 1; }
            }
        }
    } else if (wid == 8) {
        // ======== MMA issuer / notifier ========
        if (elect_one()) {
            int ls = 0; uint32_t lp = 0;        // local-full cursor
            int fs = 0; uint32_t fp = 0;        // pair-full cursor (rank 0)
            uint32_t efp[2] = {1, 1};           // epi_free cursors (fresh passes)
            for (int t = 0; t < TPP; t++) {
                const int buf = t & 1;
                const uint32_t dtm = tmem + buf * 256;
                for (int kt = 0; kt < KT; kt++) {
                    wait_parity(sb + SM_FLOC + ls * 8, lp);       // own tiles landed
                    fence_proxy_async_cta();
                    mbar_arrive_cluster(sb + SM_FULL + ls * 8, 0); // notify leader
                    if (rank == 0) {
                        if (kt == 0) {                             // D buffer drained?
                            wait_parity(sb + SM_EPIF + buf * 8, efp[buf]);
                            efp[buf] ^= 1;
                        }
                        wait_parity(sb + SM_FULL + fs * 8, fp);    // both CTAs ready
                        fence_after_sync();
                        const uint64_t ad = DESC_BASE | (((sb + SM_A + fs * TILE_B) >> 4) & 0x3FFF);
                        const uint64_t bd = DESC_BASE | (((sb + SM_B + fs * TILE_B) >> 4) & 0x3FFF);
#pragma unroll
                        for (int ks = 0; ks < 4; ks++)
                            mma_cg2_tf32(dtm, ad + ks * 2, bd + ks * 2,
                                         IDESC_TF32, (kt > 0 || ks > 0) ? 1u : 0u);
                        commit_mc(sb + SM_EMPTY + fs * 8);         // free the stage
                        if (kt == KT - 1)
                            commit_mc(sb + SM_DONE + buf * 8);     // tile complete
                        if (++fs == NSTAGE) { fs = 0; fp ^= 1; }
                    }
                    if (++ls == NSTAGE) { ls = 0; lp ^= 1; }
                }
            }
        }
    } else {
        // ======== epilogue: warps 4-7, one TMEM subpartition each ========
        const int sub  = wid - 4;
        const int lane = tid & 31;
        const int grow = m0 + sub * 32 + lane;
        float* crow = C + (size_t)grow * N;
        uint32_t dnp[2] = {0, 0};
        for (int t = 0; t < TPP; t++) {
            const int buf = t & 1;
            wait_parity(sb + SM_DONE + buf * 8, dnp[buf]);
            dnp[buf] ^= 1;
            fence_after_sync();
#pragma unroll
            for (int c4 = 0; c4 < 8; c4++) {
                uint32_t r[32];
                LDTM_X32(r, tmem + buf * 256 + c4 * 32);
                wait_ld();
                const int gc0 = t * 256 + c4 * 32;
#pragma unroll
                for (int j = 0; j < 32; j += 4) {
                    float4 bv = *(const float4*)(bias + gc0 + j);
                    float v0 = __uint_as_float(r[j])     + bv.x;
                    float v1 = __uint_as_float(r[j + 1]) + bv.y;
                    float v2 = __uint_as_float(r[j + 2]) + bv.z;
                    float v3 = __uint_as_float(r[j + 3]) + bv.w;
                    if (RELU) {   // ReLU + pre-round for GEMM2's HW truncation
                        v0 = bumpf(fmaxf(v0, 0.f)); v1 = bumpf(fmaxf(v1, 0.f));
                        v2 = bumpf(fmaxf(v2, 0.f)); v3 = bumpf(fmaxf(v3, 0.f));
                    }
                    st_cs4(crow + gc0 + j, v0, v1, v2, v3);
                }
            }
            fence_before_sync();
            mbar_arrive_cluster(sb + SM_EPIF + buf * 8, 0);   // release D buffer
        }
    }

    __syncthreads();
    if (wid == 8) tmem_dealloc_cg2(tmem, 512);
    cluster_sync();
#else
    // ================= fallback: legacy mma.sync tf32 (generic PTX pass) ========
    extern __shared__ float sm[];
    const int tid  = threadIdx.x;
    const int lane = tid & 31;
    const int wid  = tid >> 5;
    const int m0 = blockIdx.y * 256 + blockIdx.x * 128;
    const int KT = K / BK;
    const int AT = 128 * 36;
    const int BT = 256 * 36;
    const uint32_t s0 = smem_u32(sm);

    for (int t = 0; t < TPP; t++) {
        const int nb = t * 256;
        float acc[4][8][4];
        if (tid < 256) {
#pragma unroll
            for (int i = 0; i < 4; i++)
#pragma unroll
                for (int j = 0; j < 8; j++)
#pragma unroll
                    for (int c = 0; c < 4; c++) acc[i][j][c] = 0.f;
        }
        auto load_tile = [&](int kt, int st) {
            if (tid < 256) {
                const float* Ag = A  + (size_t)m0 * K + (size_t)kt * BK;
                const float* Bg = Bm + (size_t)nb * K + (size_t)kt * BK;
                const uint32_t sA = s0 + (uint32_t)(st * (AT + BT)) * 4;
                const uint32_t sB = sA + (uint32_t)AT * 4;
#pragma unroll
                for (int q = 0; q < 4; q++) {
                    int ch = tid + q * 256; int row = ch >> 3, c4 = ch & 7;
                    cp16(sA + (uint32_t)(row * 36 + c4 * 4) * 4, Ag + (size_t)row * K + c4 * 4);
                }
#pragma unroll
                for (int q = 0; q < 8; q++) {
                    int ch = tid + q * 256; int row = ch >> 3, c4 = ch & 7;
                    cp16(sB + (uint32_t)(row * 36 + c4 * 4) * 4, Bg + (size_t)row * K + c4 * 4);
                }
            }
            asm volatile("cp.async.commit_group;");
        };
        load_tile(0, 0);
        for (int kt = 0; kt < KT; kt++) {
            const int st = kt & 1;
            if (kt + 1 < KT) { load_tile(kt + 1, st ^ 1);
                               asm volatile("cp.async.wait_group 1;"); }
            else             { asm volatile("cp.async.wait_group 0;"); }
            __syncthreads();
            if (tid < 256) {
                const float* As = sm + st * (AT + BT);
                const float* Bs = As + AT;
                const int wm = wid >> 2, wn = wid & 3;
                const int g = lane >> 2, tg = lane & 3;
#pragma unroll
                for (int ks = 0; ks < 4; ks++) {
                    const int k0 = ks * 8;
                    uint32_t af[4][4], bf[8][2];
#pragma unroll
                    for (int i = 0; i < 4; i++) {
                        const int r = wm * 64 + i * 16 + g;
                        af[i][0] = __float_as_uint(As[(r    ) * 36 + k0 + tg    ]);
                        af[i][1] = __float_as_uint(As[(r + 8) * 36 + k0 + tg    ]);
                        af[i][2] = __float_as_uint(As[(r    ) * 36 + k0 + tg + 4]);
                        af[i][3] = __float_as_uint(As[(r + 8) * 36 + k0 + tg + 4]);
                    }
#pragma unroll
                    for (int j = 0; j < 8; j++) {
                        const int c = wn * 64 + j * 8 + g;
                        bf[j][0] = __float_as_uint(Bs[c * 36 + k0 + tg    ]);
                        bf[j][1] = __float_as_uint(Bs[c * 36 + k0 + tg + 4]);
                    }
#pragma unroll
                    for (int i = 0; i < 4; i++)
#pragma unroll
                        for (int j = 0; j < 8; j++)
                            mma_tf32(acc[i][j], af[i], bf[j]);
                }
            }
            __syncthreads();
        }
        if (tid < 256) {
            const int wm = wid >> 2, wn = wid & 3;
            const int g = lane >> 2, tg = lane & 3;
#pragma unroll
            for (int i = 0; i < 4; i++) {
                const int r0 = m0 + wm * 64 + i * 16 + g;
#pragma unroll
                for (int j = 0; j < 8; j++) {
                    const int c = nb + wn * 64 + j * 8 + tg * 2;
                    const float bv0 = bias[c], bv1 = bias[c + 1];
                    float v0 = acc[i][j][0] + bv0, v1 = acc[i][j][1] + bv1;
                    float v2 = acc[i][j][2] + bv0, v3 = acc[i][j][3] + bv1;
                    if (RELU) {
                        v0 = bumpf(fmaxf(v0, 0.f)); v1 = bumpf(fmaxf(v1, 0.f));
                        v2 = bumpf(fmaxf(v2, 0.f)); v3 = bumpf(fmaxf(v3, 0.f));
                    }
                    *(float2*)(C + (size_t)r0 * N + c)       = make_float2(v0, v1);
                    *(float2*)(C + (size_t)(r0 + 8) * N + c) = make_float2(v2, v3);
                }
            }
        }
        __syncthreads();
    }
#endif
}

// ---------------- launch ----------------
extern "C" void kernel_launch(void* const* d_in, const int* in_sizes, int n_in,
                              void* d_out, int out_size) {
    (void)in_sizes; (void)n_in; (void)out_size;
    const float* x  = (const float*)d_in[0];
    const float* W1 = (const float*)d_in[1];
    const float* b1 = (const float*)d_in[2];
    const float* W2 = (const float*)d_in[3];
    const float* b2 = (const float*)d_in[4];
    float* out = (float*)d_out;

    float *inter, *xb, *w1b, *w2b;
    cudaGetSymbolAddress((void**)&inter, g_inter);
    cudaGetSymbolAddress((void**)&xb,  g_xb);
    cudaGetSymbolAddress((void**)&w1b, g_w1b);
    cudaGetSymbolAddress((void**)&w2b, g_w2b);

    cudaFuncSetAttribute(ffn_gemm<true>,
                         cudaFuncAttributeMaxDynamicSharedMemorySize, SMEM_TOTAL);
    cudaFuncSetAttribute(ffn_gemm<false>,
                         cudaFuncAttributeMaxDynamicSharedMemorySize, SMEM_TOTAL);

    // Prepass: tf32-rna pre-round of X, W1, W2 (inter pre-rounded in epilogue).
    {
        int n4;
        n4 = MTOT * HID / 4;
        bump_tf32_kernel<<<(n4 + 255) / 256, 256>>>((const float4*)x,  (float4*)xb,  n4);
        n4 = ITR * HID / 4;
        bump_tf32_kernel<<<(n4 + 255) / 256, 256>>>((const float4*)W1, (float4*)w1b, n4);
        n4 = HID * ITR / 4;
        bump_tf32_kernel<<<(n4 + 255) / 256, 256>>>((const float4*)W2, (float4*)w2b, n4);
    }

    // GEMM1: inter = bump(ReLU(X @ W1^T + b1))  [16384,4096], K=1024, 16 N-tiles/pair
    ffn_gemm<true><<<dim3(2, MTOT / 256, 1), 288, SMEM_TOTAL>>>(
        xb, w1b, b1, inter, HID, ITR, ITR / 256);

    // GEMM2: out = inter @ W2^T + b2            [16384,1024], K=4096, 4 N-tiles/pair
    ffn_gemm<false><<<dim3(2, MTOT / 256, 1), 288, SMEM_TOTAL>>>(
        inter, w2b, b2, out, ITR, HID, HID / 256);
}